// round 2
// baseline (speedup 1.0000x reference)
#include <cuda_runtime.h>
#include <cuda_bf16.h>
#include <cstdint>

// ColBERT MaxSim on GB300 (sm_103a), round 1: mma.sync bf16 with fused max/sum.
// qs: (64 queries, 32 tokens, 128 dim) fp32
// ps: (64 docs, 1024 tokens, 128 dim)  fp32
// out: (64, 64) fp32  out[b,c] = sum_n max_s dot(qs[b,n,:], ps[c,s,:])

#define NQ       64
#define TQ       32
#define ND       64
#define TS       1024
#define DIM      128
#define G_Q      8                    // queries per block
#define M_ROWS   (G_Q * TQ)           // 256 query-token rows per block
#define SN       64                   // doc-token chunk
#define NCHUNK   (TS / SN)            // 16
#define BPAD     8
#define BSTRIDE  (DIM + BPAD)         // 136 halves per row (conflict-free frag loads)
#define THREADS  256                  // 8 warps; warp w <-> query qg*8+w

__device__ __forceinline__ unsigned pack_bf16(float lo, float hi) {
    __nv_bfloat162 h = __floats2bfloat162_rn(lo, hi);  // x = lo (low 16 bits)
    return *reinterpret_cast<unsigned*>(&h);
}

__device__ __forceinline__ void mma_bf16(float c[4],
                                         unsigned a0, unsigned a1, unsigned a2, unsigned a3,
                                         unsigned b0, unsigned b1) {
    asm volatile(
        "mma.sync.aligned.m16n8k16.row.col.f32.bf16.bf16.f32 "
        "{%0,%1,%2,%3}, {%4,%5,%6,%7}, {%8,%9}, {%0,%1,%2,%3};\n"
        : "+f"(c[0]), "+f"(c[1]), "+f"(c[2]), "+f"(c[3])
        : "r"(a0), "r"(a1), "r"(a2), "r"(a3), "r"(b0), "r"(b1));
}

__global__ __launch_bounds__(THREADS)
void colbert_maxsim_kernel(const float* __restrict__ qs,
                           const float* __restrict__ ps,
                           float* __restrict__ out) {
    __shared__ __nv_bfloat16 Bs[2][SN * BSTRIDE];

    const int tid   = threadIdx.x;
    const int w     = tid >> 5;        // warp id = query within group
    const int lane  = tid & 31;
    const int g     = lane >> 2;       // groupID (row within mma tile)
    const int t     = lane & 3;        // threadID_in_group (col pair)
    const int c_doc = blockIdx.x;      // doc index
    const int qg    = blockIdx.y;      // query group

    // ---- Load A fragments (this warp's query: 32 rows x 128 dims) from gmem (L2-resident) ----
    // m16n8k16 A layout: a0 = {A[g][2t],A[g][2t+1]}, a1 = rows+8, a2 = cols+8, a3 = both+8
    unsigned Af[2][8][4];
    {
        const int rbase = qg * M_ROWS + w * TQ;
        #pragma unroll
        for (int mt = 0; mt < 2; mt++) {
            #pragma unroll
            for (int ks = 0; ks < 8; ks++) {
                const int r0 = rbase + mt * 16 + g;
                const int c0 = ks * 16 + t * 2;
                const float2* p0 = reinterpret_cast<const float2*>(qs + (size_t)r0 * DIM + c0);
                const float2* p1 = reinterpret_cast<const float2*>(qs + (size_t)(r0 + 8) * DIM + c0);
                float2 v00 = p0[0];
                float2 v02 = p0[4];   // +8 columns
                float2 v10 = p1[0];
                float2 v12 = p1[4];
                Af[mt][ks][0] = pack_bf16(v00.x, v00.y);
                Af[mt][ks][1] = pack_bf16(v10.x, v10.y);
                Af[mt][ks][2] = pack_bf16(v02.x, v02.y);
                Af[mt][ks][3] = pack_bf16(v12.x, v12.y);
            }
        }
    }

    const float* pbase = ps + (size_t)c_doc * TS * DIM;

    // ---- Prologue: load + store chunk 0 into buffer 0 ----
    float4 pre[8];
    {
        const float4* src = reinterpret_cast<const float4*>(pbase);
        #pragma unroll
        for (int j = 0; j < 8; j++) pre[j] = src[j * THREADS + tid];
        #pragma unroll
        for (int j = 0; j < 8; j++) {
            const int f = j * THREADS + tid;      // float4 index in chunk (2048 total)
            const int n = f >> 5;                 // 32 float4 per token row
            const int k = (f & 31) << 2;
            uint2 u;
            u.x = pack_bf16(pre[j].x, pre[j].y);
            u.y = pack_bf16(pre[j].z, pre[j].w);
            *reinterpret_cast<uint2*>(&Bs[0][n * BSTRIDE + k]) = u;
        }
    }
    __syncthreads();

    float rmax0 = -1e30f, rmax1 = -1e30f, rmax2 = -1e30f, rmax3 = -1e30f;

    for (int ch = 0; ch < NCHUNK; ch++) {
        // Prefetch next chunk from gmem (latency hidden by compute below)
        if (ch + 1 < NCHUNK) {
            const float4* src = reinterpret_cast<const float4*>(pbase + (size_t)(ch + 1) * SN * DIM);
            #pragma unroll
            for (int j = 0; j < 8; j++) pre[j] = src[j * THREADS + tid];
        }

        // ---- Compute on current buffer ----
        const __nv_bfloat16* Bb   = Bs[ch & 1];
        const __nv_bfloat16* bptr = Bb + g * BSTRIDE + t * 2;
        #pragma unroll
        for (int nf = 0; nf < 8; nf++) {
            float c0[4] = {0.f, 0.f, 0.f, 0.f};
            float c1[4] = {0.f, 0.f, 0.f, 0.f};
            const __nv_bfloat16* bp = bptr + nf * 8 * BSTRIDE;
            #pragma unroll
            for (int ks = 0; ks < 8; ks++) {
                // B frag: b0 = {P[n][2t+16ks], P[n][2t+1+16ks]}, b1 = +8 in k
                unsigned b0 = *reinterpret_cast<const unsigned*>(bp + ks * 16);
                unsigned b1 = *reinterpret_cast<const unsigned*>(bp + ks * 16 + 8);
                mma_bf16(c0, Af[0][ks][0], Af[0][ks][1], Af[0][ks][2], Af[0][ks][3], b0, b1);
                mma_bf16(c1, Af[1][ks][0], Af[1][ks][1], Af[1][ks][2], Af[1][ks][3], b0, b1);
            }
            // Running max per mma row (c0/c1 are cols 2t,2t+1 of rows g / g+8)
            rmax0 = fmaxf(rmax0, fmaxf(c0[0], c0[1]));
            rmax1 = fmaxf(rmax1, fmaxf(c0[2], c0[3]));
            rmax2 = fmaxf(rmax2, fmaxf(c1[0], c1[1]));
            rmax3 = fmaxf(rmax3, fmaxf(c1[2], c1[3]));
        }
        __syncthreads();   // everyone done reading the buffer we are about to overwrite

        if (ch + 1 < NCHUNK) {
            __nv_bfloat16* dst = Bs[(ch + 1) & 1];
            #pragma unroll
            for (int j = 0; j < 8; j++) {
                const int f = j * THREADS + tid;
                const int n = f >> 5;
                const int k = (f & 31) << 2;
                uint2 u;
                u.x = pack_bf16(pre[j].x, pre[j].y);
                u.y = pack_bf16(pre[j].z, pre[j].w);
                *reinterpret_cast<uint2*>(&dst[n * BSTRIDE + k]) = u;
            }
            __syncthreads();
        }
    }

    // ---- Reduce: complete each row max across the 4 lanes sharing groupID ----
    #pragma unroll
    for (int off = 1; off <= 2; off <<= 1) {
        rmax0 = fmaxf(rmax0, __shfl_xor_sync(0xffffffffu, rmax0, off));
        rmax1 = fmaxf(rmax1, __shfl_xor_sync(0xffffffffu, rmax1, off));
        rmax2 = fmaxf(rmax2, __shfl_xor_sync(0xffffffffu, rmax2, off));
        rmax3 = fmaxf(rmax3, __shfl_xor_sync(0xffffffffu, rmax3, off));
    }
    // Thread (any lane in group g) now holds full maxes of rows w*32 + {g, g+8, g+16, g+24}
    float v = rmax0 + rmax1 + rmax2 + rmax3;
    // Sum across the 8 groups (values duplicated x4 within group, so only xor 4/8/16)
    v += __shfl_xor_sync(0xffffffffu, v, 4);
    v += __shfl_xor_sync(0xffffffffu, v, 8);
    v += __shfl_xor_sync(0xffffffffu, v, 16);

    if (lane == 0) {
        out[(qg * G_Q + w) * ND + c_doc] = v;
    }
}

extern "C" void kernel_launch(void* const* d_in, const int* in_sizes, int n_in,
                              void* d_out, int out_size) {
    const float* qs = (const float*)d_in[0];   // 64*32*128
    const float* ps = (const float*)d_in[1];   // 64*1024*128
    float* out = (float*)d_out;                // 64*64
    dim3 grid(ND, NQ / G_Q);                   // (64 docs, 8 query groups)
    colbert_maxsim_kernel<<<grid, THREADS>>>(qs, ps, out);
}

// round 4
// speedup vs baseline: 1.2031x; 1.2031x over previous
#include <cuda_runtime.h>
#include <cuda_fp16.h>
#include <cstdint>

// ColBERT MaxSim on GB300 (sm_103, no 'a' features): mma.sync f16 + ldmatrix + cp.async.
// qs: (64, 32, 128) fp32 ; ps: (64, 1024, 128) fp32 ; out: (64, 64) fp32
// out[b,c] = sum_n max_s dot(qs[b,n,:], ps[c,s,:])

#define NQ       64
#define TQ       32
#define ND       64
#define TS       1024
#define DIM      128
#define G_Q      4                    // queries per CTA (1 per warp)
#define THREADS  128
#define SN       64                   // doc tokens per chunk
#define NCHUNK   (TS / SN)            // 16
#define ROWB     256                  // bytes per token row in smem (128 f16)
#define BUFB     (SN * ROWB)          // 16 KB per buffer

// fp16 ps scratch (device-global; allocation-free per harness rules)
__device__ uint4 scratch_ps_v[(size_t)ND * TS * DIM / 8];   // 16 MB

__global__ void cvt_ps_kernel(const float4* __restrict__ src) {
    int i = blockIdx.x * blockDim.x + threadIdx.x;
    float4 a = src[2 * i], b = src[2 * i + 1];
    uint4 o;
    __half2 h;
    h = __floats2half2_rn(a.x, a.y); o.x = *reinterpret_cast<uint32_t*>(&h);
    h = __floats2half2_rn(a.z, a.w); o.y = *reinterpret_cast<uint32_t*>(&h);
    h = __floats2half2_rn(b.x, b.y); o.z = *reinterpret_cast<uint32_t*>(&h);
    h = __floats2half2_rn(b.z, b.w); o.w = *reinterpret_cast<uint32_t*>(&h);
    scratch_ps_v[i] = o;
}

__device__ __forceinline__ uint32_t smem_u32(const void* p) {
    uint32_t a;
    asm("{ .reg .u64 t; cvta.to.shared.u64 t, %1; cvt.u32.u64 %0, t; }" : "=r"(a) : "l"(p));
    return a;
}

__device__ __forceinline__ unsigned pack_h2(float lo, float hi) {
    __half2 h = __floats2half2_rn(lo, hi);
    return *reinterpret_cast<unsigned*>(&h);
}

__device__ __forceinline__ void mma_f16(float c[4],
                                        unsigned a0, unsigned a1, unsigned a2, unsigned a3,
                                        unsigned b0, unsigned b1) {
    asm volatile(
        "mma.sync.aligned.m16n8k16.row.col.f32.f16.f16.f32 "
        "{%0,%1,%2,%3}, {%4,%5,%6,%7}, {%8,%9}, {%0,%1,%2,%3};\n"
        : "+f"(c[0]), "+f"(c[1]), "+f"(c[2]), "+f"(c[3])
        : "r"(a0), "r"(a1), "r"(a2), "r"(a3), "r"(b0), "r"(b1));
}

__global__ __launch_bounds__(THREADS)
void colbert_kernel(const float* __restrict__ qs, float* __restrict__ out) {
    __shared__ __align__(1024) char Bs[2 * BUFB];

    const int tid   = threadIdx.x;
    const int w     = tid >> 5;          // warp = query within group
    const int lane  = tid & 31;
    const int g     = lane >> 2;
    const int t     = lane & 3;
    const int c_doc = blockIdx.x;
    const int qg    = blockIdx.y;
    const uint32_t sb = smem_u32(Bs);

    const uint4* gsrc = scratch_ps_v + (size_t)c_doc * TS * DIM / 8;

    // ---- prologue: async-copy chunk 0 into buffer 0 (XOR-swizzled rows) ----
    #pragma unroll
    for (int j = 0; j < 8; j++) {
        int f = j * THREADS + tid;       // 16B unit index, 1024 per chunk
        int r = f >> 4;                  // token row (16 units per 256B row)
        int c = f & 15;                  // 16B chunk within row
        uint32_t dst = sb + r * ROWB + ((c ^ (r & 7)) << 4);
        asm volatile("cp.async.cg.shared.global [%0], [%1], 16;\n" :: "r"(dst), "l"(gsrc + f));
    }
    asm volatile("cp.async.commit_group;\n");

    // ---- A fragments: this warp's query (32 rows x 128 dims), fp32 -> f16 packed ----
    // m16n8k16 A layout: a0={A[g][2t],A[g][2t+1]}, a1=rows+8, a2=cols+8, a3=both+8
    unsigned Af[2][8][4];
    {
        const int rbase = (qg * G_Q + w) * TQ;
        #pragma unroll
        for (int mt = 0; mt < 2; mt++) {
            #pragma unroll
            for (int ks = 0; ks < 8; ks++) {
                const int r0 = rbase + mt * 16 + g;
                const int cc = ks * 16 + t * 2;
                const float2* p0 = reinterpret_cast<const float2*>(qs + (size_t)r0 * DIM + cc);
                const float2* p1 = reinterpret_cast<const float2*>(qs + (size_t)(r0 + 8) * DIM + cc);
                float2 v00 = p0[0];
                float2 v02 = p0[4];
                float2 v10 = p1[0];
                float2 v12 = p1[4];
                Af[mt][ks][0] = pack_h2(v00.x, v00.y);
                Af[mt][ks][1] = pack_h2(v10.x, v10.y);
                Af[mt][ks][2] = pack_h2(v02.x, v02.y);
                Af[mt][ks][3] = pack_h2(v12.x, v12.y);
            }
        }
    }

    float rmax0 = -1e30f, rmax1 = -1e30f, rmax2 = -1e30f, rmax3 = -1e30f;

    const int rl = lane & 7;             // row provider within 8x8 matrix
    const int mc = lane >> 3;            // which of the 4 matrices this lane addresses

    #pragma unroll 1
    for (int ch = 0; ch < NCHUNK; ch++) {
        if (ch + 1 < NCHUNK) {
            const uint4* gs2  = gsrc + (size_t)(ch + 1) * SN * DIM / 8;
            uint32_t     dbuf = sb + ((ch + 1) & 1) * BUFB;
            #pragma unroll
            for (int j = 0; j < 8; j++) {
                int f = j * THREADS + tid;
                int r = f >> 4;
                int c = f & 15;
                uint32_t dst = dbuf + r * ROWB + ((c ^ (r & 7)) << 4);
                asm volatile("cp.async.cg.shared.global [%0], [%1], 16;\n" :: "r"(dst), "l"(gs2 + f));
            }
            asm volatile("cp.async.commit_group;\n");
            asm volatile("cp.async.wait_group 1;\n");
        } else {
            asm volatile("cp.async.wait_group 0;\n");
        }
        __syncthreads();

        // ---- compute on buffer ch&1 ----
        const uint32_t cbase = sb + (ch & 1) * BUFB + rl * ROWB;
        #pragma unroll
        for (int nf = 0; nf < 8; nf++) {
            float c0[4] = {0.f, 0.f, 0.f, 0.f};
            float c1[4] = {0.f, 0.f, 0.f, 0.f};
            #pragma unroll
            for (int kp = 0; kp < 4; kp++) {
                // x4 matrices: (ks=2kp,b0), (ks=2kp,b1), (ks=2kp+1,b0), (ks=2kp+1,b1)
                uint32_t addr = cbase + nf * 8 * ROWB + ((((kp << 2) | mc) ^ rl) << 4);
                uint32_t b0, b1, b2, b3;
                asm volatile("ldmatrix.sync.aligned.m8n8.x4.shared.b16 {%0,%1,%2,%3}, [%4];\n"
                             : "=r"(b0), "=r"(b1), "=r"(b2), "=r"(b3) : "r"(addr));
                mma_f16(c0, Af[0][2*kp][0],   Af[0][2*kp][1],   Af[0][2*kp][2],   Af[0][2*kp][3],   b0, b1);
                mma_f16(c1, Af[1][2*kp][0],   Af[1][2*kp][1],   Af[1][2*kp][2],   Af[1][2*kp][3],   b0, b1);
                mma_f16(c0, Af[0][2*kp+1][0], Af[0][2*kp+1][1], Af[0][2*kp+1][2], Af[0][2*kp+1][3], b2, b3);
                mma_f16(c1, Af[1][2*kp+1][0], Af[1][2*kp+1][1], Af[1][2*kp+1][2], Af[1][2*kp+1][3], b2, b3);
            }
            rmax0 = fmaxf(rmax0, fmaxf(c0[0], c0[1]));
            rmax1 = fmaxf(rmax1, fmaxf(c0[2], c0[3]));
            rmax2 = fmaxf(rmax2, fmaxf(c1[0], c1[1]));
            rmax3 = fmaxf(rmax3, fmaxf(c1[2], c1[3]));
        }
        __syncthreads();   // all warps done reading before this buffer is overwritten
    }

    // ---- reduce: complete row maxes across the 4 lanes sharing g ----
    #pragma unroll
    for (int off = 1; off <= 2; off <<= 1) {
        rmax0 = fmaxf(rmax0, __shfl_xor_sync(0xffffffffu, rmax0, off));
        rmax1 = fmaxf(rmax1, __shfl_xor_sync(0xffffffffu, rmax1, off));
        rmax2 = fmaxf(rmax2, __shfl_xor_sync(0xffffffffu, rmax2, off));
        rmax3 = fmaxf(rmax3, __shfl_xor_sync(0xffffffffu, rmax3, off));
    }
    float v = rmax0 + rmax1 + rmax2 + rmax3;   // rows {g, g+8, g+16, g+24}
    v += __shfl_xor_sync(0xffffffffu, v, 4);
    v += __shfl_xor_sync(0xffffffffu, v, 8);
    v += __shfl_xor_sync(0xffffffffu, v, 16);

    if (lane == 0) {
        out[(qg * G_Q + w) * ND + c_doc] = v;
    }
}

extern "C" void kernel_launch(void* const* d_in, const int* in_sizes, int n_in,
                              void* d_out, int out_size) {
    const float* qs = (const float*)d_in[0];   // 64*32*128
    const float* ps = (const float*)d_in[1];   // 64*1024*128
    float* out = (float*)d_out;                // 64*64

    cvt_ps_kernel<<<(ND * TS * DIM / 8) / 256, 256>>>((const float4*)ps);

    dim3 grid(ND, NQ / G_Q);                   // (64 docs, 16 query groups)
    colbert_kernel<<<grid, THREADS>>>(qs, out);
}

// round 5
// speedup vs baseline: 1.2412x; 1.0317x over previous
#include <cuda_runtime.h>
#include <cuda_fp16.h>
#include <cstdint>

// ColBERT MaxSim on GB300 (sm_103): mma.sync f16 + ldmatrix + cp.async, 4 CTA/SM.
// qs: (64, 32, 128) fp32 ; ps: (64, 1024, 128) fp32 ; out: (64, 64) fp32
// out[b,c] = sum_n max_s dot(qs[b,n,:], ps[c,s,:])

#define NQ       64
#define TQ       32
#define ND       64
#define TS       1024
#define DIM      128
#define G_Q      4                    // queries per CTA (1 per warp)
#define THREADS  128
#define SN       64                   // doc tokens per chunk
#define NCHUNK   (TS / SN)            // 16
#define ROWB     256                  // bytes per token row in smem (128 f16)
#define BUFB     (SN * ROWB)          // 16 KB per buffer

// fp16 ps scratch (device-global; allocation-free per harness rules)
__device__ uint4 scratch_ps_v[(size_t)ND * TS * DIM / 8];   // 16 MB

__global__ void cvt_ps_kernel(const float4* __restrict__ src) {
    int i = blockIdx.x * blockDim.x + threadIdx.x;
    float4 a = src[2 * i], b = src[2 * i + 1];
    uint4 o;
    __half2 h;
    h = __floats2half2_rn(a.x, a.y); o.x = *reinterpret_cast<uint32_t*>(&h);
    h = __floats2half2_rn(a.z, a.w); o.y = *reinterpret_cast<uint32_t*>(&h);
    h = __floats2half2_rn(b.x, b.y); o.z = *reinterpret_cast<uint32_t*>(&h);
    h = __floats2half2_rn(b.z, b.w); o.w = *reinterpret_cast<uint32_t*>(&h);
    scratch_ps_v[i] = o;
}

__device__ __forceinline__ uint32_t smem_u32(const void* p) {
    uint32_t a;
    asm("{ .reg .u64 t; cvta.to.shared.u64 t, %1; cvt.u32.u64 %0, t; }" : "=r"(a) : "l"(p));
    return a;
}

__device__ __forceinline__ unsigned pack_h2(float lo, float hi) {
    __half2 h = __floats2half2_rn(lo, hi);
    return *reinterpret_cast<unsigned*>(&h);
}

__device__ __forceinline__ void mma_f16(float c[4],
                                        unsigned a0, unsigned a1, unsigned a2, unsigned a3,
                                        unsigned b0, unsigned b1) {
    asm volatile(
        "mma.sync.aligned.m16n8k16.row.col.f32.f16.f16.f32 "
        "{%0,%1,%2,%3}, {%4,%5,%6,%7}, {%8,%9}, {%0,%1,%2,%3};\n"
        : "+f"(c[0]), "+f"(c[1]), "+f"(c[2]), "+f"(c[3])
        : "r"(a0), "r"(a1), "r"(a2), "r"(a3), "r"(b0), "r"(b1));
}

__global__ __launch_bounds__(THREADS, 4)
void colbert_kernel(const float* __restrict__ qs, float* __restrict__ out) {
    __shared__ __align__(1024) char Bs[2 * BUFB];

    const int tid   = threadIdx.x;
    const int w     = tid >> 5;          // warp = query within group
    const int lane  = tid & 31;
    const int g     = lane >> 2;
    const int t     = lane & 3;
    const int c_doc = blockIdx.x;
    const int qg    = blockIdx.y;
    const uint32_t sb = smem_u32(Bs);

    const uint4* gsrc = scratch_ps_v + (size_t)c_doc * TS * DIM / 8;

    // ---- prologue: async-copy chunk 0 into buffer 0 (XOR-swizzled rows) ----
    #pragma unroll
    for (int j = 0; j < 8; j++) {
        int f = j * THREADS + tid;       // 16B unit index, 1024 per chunk
        int r = f >> 4;                  // token row (16 units per 256B row)
        int c = f & 15;                  // 16B chunk within row
        uint32_t dst = sb + r * ROWB + ((c ^ (r & 7)) << 4);
        asm volatile("cp.async.cg.shared.global [%0], [%1], 16;\n" :: "r"(dst), "l"(gsrc + f));
    }
    asm volatile("cp.async.commit_group;\n");

    // ---- A fragments: this warp's query (32 rows x 128 dims), fp32 -> f16 packed ----
    // m16n8k16 A layout: a0={A[g][2t],A[g][2t+1]}, a1=rows+8, a2=cols+8, a3=both+8
    unsigned Af[2][8][4];
    {
        const int rbase = (qg * G_Q + w) * TQ;
        #pragma unroll
        for (int mt = 0; mt < 2; mt++) {
            #pragma unroll
            for (int ks = 0; ks < 8; ks++) {
                const int r0 = rbase + mt * 16 + g;
                const int cc = ks * 16 + t * 2;
                const float2* p0 = reinterpret_cast<const float2*>(qs + (size_t)r0 * DIM + cc);
                const float2* p1 = reinterpret_cast<const float2*>(qs + (size_t)(r0 + 8) * DIM + cc);
                float2 v00 = p0[0];
                float2 v02 = p0[4];
                float2 v10 = p1[0];
                float2 v12 = p1[4];
                Af[mt][ks][0] = pack_h2(v00.x, v00.y);
                Af[mt][ks][1] = pack_h2(v10.x, v10.y);
                Af[mt][ks][2] = pack_h2(v02.x, v02.y);
                Af[mt][ks][3] = pack_h2(v12.x, v12.y);
            }
        }
    }

    float rmax0 = -1e30f, rmax1 = -1e30f, rmax2 = -1e30f, rmax3 = -1e30f;

    const int rl = lane & 7;             // row provider within 8x8 matrix
    const int mc = lane >> 3;            // which of the 4 matrices this lane addresses

    // Single-sync pipeline: at top of iteration ch,
    //   wait_group(0): chunk ch's copies (issued at iter ch-1) complete
    //   __syncthreads(): data visible to all + all warps done reading buf[(ch+1)&1] (chunk ch-1)
    //   issue copies for ch+1 (overlap with compute of ch)
    #pragma unroll 1
    for (int ch = 0; ch < NCHUNK; ch++) {
        asm volatile("cp.async.wait_group 0;\n");
        __syncthreads();

        if (ch + 1 < NCHUNK) {
            const uint4* gs2  = gsrc + (size_t)(ch + 1) * SN * DIM / 8;
            uint32_t     dbuf = sb + ((ch + 1) & 1) * BUFB;
            #pragma unroll
            for (int j = 0; j < 8; j++) {
                int f = j * THREADS + tid;
                int r = f >> 4;
                int c = f & 15;
                uint32_t dst = dbuf + r * ROWB + ((c ^ (r & 7)) << 4);
                asm volatile("cp.async.cg.shared.global [%0], [%1], 16;\n" :: "r"(dst), "l"(gs2 + f));
            }
            asm volatile("cp.async.commit_group;\n");
        }

        // ---- compute on buffer ch&1 ----
        const uint32_t cbase = sb + (ch & 1) * BUFB + rl * ROWB;
        #pragma unroll
        for (int nf = 0; nf < 8; nf++) {
            float c0[4] = {0.f, 0.f, 0.f, 0.f};
            float c1[4] = {0.f, 0.f, 0.f, 0.f};
            #pragma unroll
            for (int kp = 0; kp < 4; kp++) {
                // x4 matrices: (ks=2kp,b0), (ks=2kp,b1), (ks=2kp+1,b0), (ks=2kp+1,b1)
                uint32_t addr = cbase + nf * 8 * ROWB + ((((kp << 2) | mc) ^ rl) << 4);
                uint32_t b0, b1, b2, b3;
                asm volatile("ldmatrix.sync.aligned.m8n8.x4.shared.b16 {%0,%1,%2,%3}, [%4];\n"
                             : "=r"(b0), "=r"(b1), "=r"(b2), "=r"(b3) : "r"(addr));
                mma_f16(c0, Af[0][2*kp][0],   Af[0][2*kp][1],   Af[0][2*kp][2],   Af[0][2*kp][3],   b0, b1);
                mma_f16(c1, Af[1][2*kp][0],   Af[1][2*kp][1],   Af[1][2*kp][2],   Af[1][2*kp][3],   b0, b1);
                mma_f16(c0, Af[0][2*kp+1][0], Af[0][2*kp+1][1], Af[0][2*kp+1][2], Af[0][2*kp+1][3], b2, b3);
                mma_f16(c1, Af[1][2*kp+1][0], Af[1][2*kp+1][1], Af[1][2*kp+1][2], Af[1][2*kp+1][3], b2, b3);
            }
            rmax0 = fmaxf(rmax0, fmaxf(c0[0], c0[1]));
            rmax1 = fmaxf(rmax1, fmaxf(c0[2], c0[3]));
            rmax2 = fmaxf(rmax2, fmaxf(c1[0], c1[1]));
            rmax3 = fmaxf(rmax3, fmaxf(c1[2], c1[3]));
        }
    }

    // ---- reduce: complete row maxes across the 4 lanes sharing g ----
    #pragma unroll
    for (int off = 1; off <= 2; off <<= 1) {
        rmax0 = fmaxf(rmax0, __shfl_xor_sync(0xffffffffu, rmax0, off));
        rmax1 = fmaxf(rmax1, __shfl_xor_sync(0xffffffffu, rmax1, off));
        rmax2 = fmaxf(rmax2, __shfl_xor_sync(0xffffffffu, rmax2, off));
        rmax3 = fmaxf(rmax3, __shfl_xor_sync(0xffffffffu, rmax3, off));
    }
    float v = rmax0 + rmax1 + rmax2 + rmax3;   // rows {g, g+8, g+16, g+24}
    v += __shfl_xor_sync(0xffffffffu, v, 4);
    v += __shfl_xor_sync(0xffffffffu, v, 8);
    v += __shfl_xor_sync(0xffffffffu, v, 16);

    if (lane == 0) {
        out[(qg * G_Q + w) * ND + c_doc] = v;
    }
}

extern "C" void kernel_launch(void* const* d_in, const int* in_sizes, int n_in,
                              void* d_out, int out_size) {
    const float* qs = (const float*)d_in[0];   // 64*32*128
    const float* ps = (const float*)d_in[1];   // 64*1024*128
    float* out = (float*)d_out;                // 64*64

    cvt_ps_kernel<<<(ND * TS * DIM / 8) / 256, 256>>>((const float4*)ps);

    dim3 grid(ND, NQ / G_Q);                   // (64 docs, 16 query groups)
    colbert_kernel<<<grid, THREADS>>>(qs, out);
}